// round 5
// baseline (speedup 1.0000x reference)
#include <cuda_runtime.h>

// ---------------------------------------------------------------------------
// MPNN layer, fused:
//   K0: zero aggr-sum + counts scratch
//   K1: per-edge MLP (131->128 relu ->64) + atomic scatter-add into aggr/cnt
//   K2: per-node mean + MLP (128->128 relu ->64) -> out
// fp32 throughout; inner products use Blackwell packed fma.rn.f32x2.
// Weights live in SMEM; 8 edges/nodes per warp amortize weight LDS traffic.
// ---------------------------------------------------------------------------

#define MAXN 65536
__device__ float g_aggr[MAXN * 64];
__device__ float g_cnt[MAXN];

typedef unsigned long long ull;

__device__ __forceinline__ ull pk2(float a, float b) {
    ull r; asm("mov.b64 %0, {%1, %2};" : "=l"(r) : "f"(a), "f"(b)); return r;
}
__device__ __forceinline__ float2 upk2(ull v) {
    float2 r; asm("mov.b64 {%0, %1}, %2;" : "=f"(r.x), "=f"(r.y) : "l"(v)); return r;
}
__device__ __forceinline__ ull ffma2(ull a, ull b, ull c) {
    ull d; asm("fma.rn.f32x2 %0, %1, %2, %3;" : "=l"(d) : "l"(a), "l"(b), "l"(c)); return d;
}

// ---------------------------- zero scratch ---------------------------------
__global__ void zero_kernel(int n_aggr4, int n) {
    int stride = gridDim.x * blockDim.x;
    int t0 = blockIdx.x * blockDim.x + threadIdx.x;
    float4* a4 = (float4*)g_aggr;
    for (int i = t0; i < n_aggr4; i += stride) a4[i] = make_float4(0.f, 0.f, 0.f, 0.f);
    for (int i = t0; i < n; i += stride) g_cnt[i] = 0.f;
}

// ---------------------------- edge kernel ----------------------------------
#define EPW 8       // edges per warp per iteration
#define EWARPS 16
#define ETHREADS 512

// float offsets in dynamic smem
#define E_W1   0            // 132*128 (row 131 zero-padded)
#define E_B1   16896        // 128
#define E_W2   17024        // 128*64
#define E_B2   25216        // 64
#define E_BUF  25280        // 16 warps * 8 edges * 132
#define E_IDX  42176        // 16 warps * 8 ints
#define E_SMEMF 42304
#define E_SMEMB (E_SMEMF * 4)

__global__ __launch_bounds__(ETHREADS, 1)
void edge_kernel(const float* __restrict__ x, const float* __restrict__ pos,
                 const int* __restrict__ idxI, const int* __restrict__ idxJ,
                 const float* __restrict__ W1, const float* __restrict__ b1,
                 const float* __restrict__ W2, const float* __restrict__ b2,
                 int E) {
    extern __shared__ float sm[];
    int tid = threadIdx.x;

    // stage weights in SMEM (W1 padded to 132 rows so k-loop can step by 2)
    {
        float4* d = (float4*)(sm + E_W1);
        const float4* s = (const float4*)W1;
        for (int t = tid; t < 4192; t += ETHREADS) d[t] = s[t];          // 131*128/4
        for (int t = tid; t < 32; t += ETHREADS) d[4192 + t] = make_float4(0.f,0.f,0.f,0.f);
        float4* d1 = (float4*)(sm + E_B1); const float4* s1 = (const float4*)b1;
        for (int t = tid; t < 32; t += ETHREADS) d1[t] = s1[t];
        float4* d2 = (float4*)(sm + E_W2); const float4* s2 = (const float4*)W2;
        for (int t = tid; t < 2048; t += ETHREADS) d2[t] = s2[t];
        float4* d3 = (float4*)(sm + E_B2); const float4* s3 = (const float4*)b2;
        for (int t = tid; t < 16; t += ETHREADS) d3[t] = s3[t];
    }
    __syncthreads();

    int warp = tid >> 5, lane = tid & 31;
    float* buf = sm + E_BUF + warp * (EPW * 132);
    int* sidx = (int*)(sm + E_IDX) + warp * EPW;

    ull hb0 = pk2(sm[E_B1 + lane*4],     sm[E_B1 + lane*4 + 1]);
    ull hb1 = pk2(sm[E_B1 + lane*4 + 2], sm[E_B1 + lane*4 + 3]);
    ull mb  = pk2(sm[E_B2 + lane*2],     sm[E_B2 + lane*2 + 1]);
    const float* w1p = sm + E_W1 + lane*4;
    const float* w2p = sm + E_W2 + lane*2;

    int ngroups = (E + EPW - 1) / EPW;
    int gwarp = blockIdx.x * EWARPS + warp;
    int nwarp = gridDim.x * EWARPS;

    for (int g = gwarp; g < ngroups; g += nwarp) {
        int base = g * EPW;

        // ---- gather msg_in = [x_i, x_j - x_i, pos_j - pos_i] (pad to 132) ----
        #pragma unroll
        for (int e = 0; e < EPW; e++) {
            int ei = base + e;
            if (ei < E) {
                int i = idxI[ei], j = idxJ[ei];
                if (lane == 0) sidx[e] = i;
                if (lane < 16) {
                    const float4* xi = (const float4*)(x + (size_t)i * 64);
                    const float4* xj = (const float4*)(x + (size_t)j * 64);
                    float4 a = xi[lane], b = xj[lane];
                    float4* pb = (float4*)(buf + e * 132);
                    pb[lane] = a;
                    pb[16 + lane] = make_float4(b.x - a.x, b.y - a.y, b.z - a.z, b.w - a.w);
                }
                if (lane >= 28) {
                    int c = lane - 28;
                    buf[e*132 + 128 + c] =
                        (c < 3) ? (pos[(size_t)j*3 + c] - pos[(size_t)i*3 + c]) : 0.f;
                }
            } else {
                if (lane == 0) sidx[e] = -1;
                for (int t = lane; t < 132; t += 32) buf[e*132 + t] = 0.f;
            }
        }
        __syncwarp();

        // ---- phase 1: hidden = relu(msg_in @ W1 + b1); lane owns cols 4l..4l+3
        ull a0[EPW], a1[EPW];
        #pragma unroll
        for (int e = 0; e < EPW; e++) { a0[e] = hb0; a1[e] = hb1; }
        #pragma unroll 2
        for (int k = 0; k < 132; k += 2) {
            float4 wA = *(const float4*)(w1p + k * 128);
            float4 wB = *(const float4*)(w1p + (k + 1) * 128);
            ull wA01 = pk2(wA.x, wA.y), wA23 = pk2(wA.z, wA.w);
            ull wB01 = pk2(wB.x, wB.y), wB23 = pk2(wB.z, wB.w);
            #pragma unroll
            for (int e = 0; e < EPW; e++) {
                float2 v = *(const float2*)(buf + e*132 + k);
                ull v0 = pk2(v.x, v.x);
                ull v1 = pk2(v.y, v.y);
                a0[e] = ffma2(wA01, v0, a0[e]);
                a1[e] = ffma2(wA23, v0, a1[e]);
                a0[e] = ffma2(wB01, v1, a0[e]);
                a1[e] = ffma2(wB23, v1, a1[e]);
            }
        }
        __syncwarp();
        #pragma unroll
        for (int e = 0; e < EPW; e++) {
            float2 p = upk2(a0[e]);
            float2 q = upk2(a1[e]);
            *(float4*)(buf + e*132 + lane*4) =
                make_float4(fmaxf(p.x,0.f), fmaxf(p.y,0.f), fmaxf(q.x,0.f), fmaxf(q.y,0.f));
        }
        __syncwarp();

        // ---- phase 2: msg = hidden @ W2 + b2; lane owns cols 2l, 2l+1 ----
        ull m[EPW];
        #pragma unroll
        for (int e = 0; e < EPW; e++) m[e] = mb;
        #pragma unroll 2
        for (int k = 0; k < 128; k += 2) {
            float2 wA = *(const float2*)(w2p + k * 64);
            float2 wB = *(const float2*)(w2p + (k + 1) * 64);
            ull wAp = pk2(wA.x, wA.y);
            ull wBp = pk2(wB.x, wB.y);
            #pragma unroll
            for (int e = 0; e < EPW; e++) {
                float2 h = *(const float2*)(buf + e*132 + k);
                m[e] = ffma2(wAp, pk2(h.x, h.x), m[e]);
                m[e] = ffma2(wBp, pk2(h.y, h.y), m[e]);
            }
        }

        // ---- scatter-add into aggr + counts ----
        #pragma unroll
        for (int e = 0; e < EPW; e++) {
            int i = sidx[e];
            if (i >= 0) {
                float2 r = upk2(m[e]);
                float* dst = g_aggr + (size_t)i * 64 + lane * 2;
                atomicAdd(dst,     r.x);
                atomicAdd(dst + 1, r.y);
            }
        }
        if (lane < EPW) {
            int i = sidx[lane];
            if (i >= 0) atomicAdd(g_cnt + i, 1.0f);
        }
        __syncwarp();
    }
}

// ---------------------------- node kernel ----------------------------------
#define NPW 8
#define N_W3   0            // 128*128
#define N_B3   16384        // 128
#define N_W4   16512        // 128*64
#define N_B4   24704        // 64
#define N_BUF  24768        // 16 warps * 8 nodes * 128
#define N_SMEMF 41152
#define N_SMEMB (N_SMEMF * 4)

__global__ __launch_bounds__(ETHREADS, 1)
void node_kernel(const float* __restrict__ x,
                 const float* __restrict__ W3, const float* __restrict__ b3,
                 const float* __restrict__ W4, const float* __restrict__ b4,
                 float* __restrict__ out, int N) {
    extern __shared__ float sm[];
    int tid = threadIdx.x;
    {
        float4* d = (float4*)(sm + N_W3); const float4* s = (const float4*)W3;
        for (int t = tid; t < 4096; t += ETHREADS) d[t] = s[t];
        float4* d1 = (float4*)(sm + N_B3); const float4* s1 = (const float4*)b3;
        for (int t = tid; t < 32; t += ETHREADS) d1[t] = s1[t];
        float4* d2 = (float4*)(sm + N_W4); const float4* s2 = (const float4*)W4;
        for (int t = tid; t < 2048; t += ETHREADS) d2[t] = s2[t];
        float4* d3 = (float4*)(sm + N_B4); const float4* s3 = (const float4*)b4;
        for (int t = tid; t < 16; t += ETHREADS) d3[t] = s3[t];
    }
    __syncthreads();

    int warp = tid >> 5, lane = tid & 31;
    float* buf = sm + N_BUF + warp * (NPW * 128);
    ull hb0 = pk2(sm[N_B3 + lane*4],     sm[N_B3 + lane*4 + 1]);
    ull hb1 = pk2(sm[N_B3 + lane*4 + 2], sm[N_B3 + lane*4 + 3]);
    ull ob  = pk2(sm[N_B4 + lane*2],     sm[N_B4 + lane*2 + 1]);
    const float* w3p = sm + N_W3 + lane*4;
    const float* w4p = sm + N_W4 + lane*2;

    int ngroups = (N + NPW - 1) / NPW;
    int gwarp = blockIdx.x * EWARPS + warp;
    int nwarp = gridDim.x * EWARPS;

    for (int g = gwarp; g < ngroups; g += nwarp) {
        int base = g * NPW;

        // gather upd_in = [x_n, aggr_n / max(cnt,1)]
        #pragma unroll
        for (int u = 0; u < NPW; u++) {
            int n = base + u;
            if (n < N) {
                if (lane < 16) {
                    float inv = 1.0f / fmaxf(g_cnt[n], 1.0f);
                    const float4* xn = (const float4*)(x + (size_t)n * 64);
                    const float4* an = (const float4*)(g_aggr + (size_t)n * 64);
                    float4 a = xn[lane], b = an[lane];
                    float4* pb = (float4*)(buf + u * 128);
                    pb[lane] = a;
                    pb[16 + lane] = make_float4(b.x*inv, b.y*inv, b.z*inv, b.w*inv);
                }
            } else {
                for (int t = lane; t < 128; t += 32) buf[u*128 + t] = 0.f;
            }
        }
        __syncwarp();

        // phase 1: relu(upd_in @ W3 + b3)
        ull a0[NPW], a1[NPW];
        #pragma unroll
        for (int u = 0; u < NPW; u++) { a0[u] = hb0; a1[u] = hb1; }
        #pragma unroll 2
        for (int k = 0; k < 128; k += 2) {
            float4 wA = *(const float4*)(w3p + k * 128);
            float4 wB = *(const float4*)(w3p + (k + 1) * 128);
            ull wA01 = pk2(wA.x, wA.y), wA23 = pk2(wA.z, wA.w);
            ull wB01 = pk2(wB.x, wB.y), wB23 = pk2(wB.z, wB.w);
            #pragma unroll
            for (int u = 0; u < NPW; u++) {
                float2 v = *(const float2*)(buf + u*128 + k);
                ull v0 = pk2(v.x, v.x);
                ull v1 = pk2(v.y, v.y);
                a0[u] = ffma2(wA01, v0, a0[u]);
                a1[u] = ffma2(wA23, v0, a1[u]);
                a0[u] = ffma2(wB01, v1, a0[u]);
                a1[u] = ffma2(wB23, v1, a1[u]);
            }
        }
        __syncwarp();
        #pragma unroll
        for (int u = 0; u < NPW; u++) {
            float2 p = upk2(a0[u]);
            float2 q = upk2(a1[u]);
            *(float4*)(buf + u*128 + lane*4) =
                make_float4(fmaxf(p.x,0.f), fmaxf(p.y,0.f), fmaxf(q.x,0.f), fmaxf(q.y,0.f));
        }
        __syncwarp();

        // phase 2: out = hidden @ W4 + b4
        ull m[NPW];
        #pragma unroll
        for (int u = 0; u < NPW; u++) m[u] = ob;
        #pragma unroll 2
        for (int k = 0; k < 128; k += 2) {
            float2 wA = *(const float2*)(w4p + k * 64);
            float2 wB = *(const float2*)(w4p + (k + 1) * 64);
            ull wAp = pk2(wA.x, wA.y);
            ull wBp = pk2(wB.x, wB.y);
            #pragma unroll
            for (int u = 0; u < NPW; u++) {
                float2 h = *(const float2*)(buf + u*128 + k);
                m[u] = ffma2(wAp, pk2(h.x, h.x), m[u]);
                m[u] = ffma2(wBp, pk2(h.y, h.y), m[u]);
            }
        }
        #pragma unroll
        for (int u = 0; u < NPW; u++) {
            int n = base + u;
            if (n < N) {
                float2 r = upk2(m[u]);
                *(float2*)(out + (size_t)n * 64 + lane * 2) = r;
            }
        }
        __syncwarp();
    }
}

// ---------------------------- launch ---------------------------------------
extern "C" void kernel_launch(void* const* d_in, const int* in_sizes, int n_in,
                              void* d_out, int out_size) {
    const float* x   = (const float*)d_in[0];
    const float* pos = (const float*)d_in[1];
    const int*   ei  = (const int*)d_in[2];
    const float* W1  = (const float*)d_in[3];
    const float* b1  = (const float*)d_in[4];
    const float* W2  = (const float*)d_in[5];
    const float* b2  = (const float*)d_in[6];
    const float* W3  = (const float*)d_in[7];
    const float* b3  = (const float*)d_in[8];
    const float* W4  = (const float*)d_in[9];
    const float* b4  = (const float*)d_in[10];
    int N = in_sizes[0] / 64;
    int E = in_sizes[2] / 2;

    cudaFuncSetAttribute(edge_kernel, cudaFuncAttributeMaxDynamicSharedMemorySize, E_SMEMB);
    cudaFuncSetAttribute(node_kernel, cudaFuncAttributeMaxDynamicSharedMemorySize, N_SMEMB);

    zero_kernel<<<512, 256>>>(N * 16, N);
    edge_kernel<<<304, ETHREADS, E_SMEMB>>>(x, pos, ei, ei + E, W1, b1, W2, b2, E);
    node_kernel<<<304, ETHREADS, N_SMEMB>>>(x, W3, b3, W4, b4, (float*)d_out, N);
}

// round 9
// speedup vs baseline: 2.0985x; 2.0985x over previous
#include <cuda_runtime.h>
#include <cstdint>

// ---------------------------------------------------------------------------
// MPNN layer, algebraically decomposed, conservative-construct build:
//   K0: zero aggr/cnt
//   Kpre: U = x@(W1a-W1b)+b1, V = x@W1b   (hoists 13.4 of 20 GFMA out of edges)
//   Kedge: hidden = relu(U[i]+V[j]+relpos@W1p); msg = hidden@W2+b2;
//          scalar atomicAdd scatter into aggr + cnt (R5-proven pattern)
//   Knode: mean + MLP (128->128 relu ->64) -> out
// No red.v4 / float3 / 64-bit shfl — only constructs proven in the R5 pass.
// ---------------------------------------------------------------------------

#define MAXN 65536
__device__ float g_aggr[MAXN * 64];
__device__ float g_cnt[MAXN];
__device__ float g_u[MAXN * 128];
__device__ float g_v[MAXN * 128];

typedef unsigned long long ull;

__device__ __forceinline__ ull pk2(float a, float b) {
    ull r; asm("mov.b64 %0, {%1, %2};" : "=l"(r) : "f"(a), "f"(b)); return r;
}
__device__ __forceinline__ float2 upk2(ull v) {
    float2 r; asm("mov.b64 {%0, %1}, %2;" : "=f"(r.x), "=f"(r.y) : "l"(v)); return r;
}
__device__ __forceinline__ ull ffma2(ull a, ull b, ull c) {
    ull d; asm("fma.rn.f32x2 %0, %1, %2, %3;" : "=l"(d) : "l"(a), "l"(b), "l"(c)); return d;
}

// ---------------------------- zero scratch ---------------------------------
__global__ void zero_kernel(int n_aggr4, int n) {
    int stride = gridDim.x * blockDim.x;
    int t0 = blockIdx.x * blockDim.x + threadIdx.x;
    float4* a4 = (float4*)g_aggr;
    for (int i = t0; i < n_aggr4; i += stride) a4[i] = make_float4(0.f, 0.f, 0.f, 0.f);
    for (int i = t0; i < n; i += stride) g_cnt[i] = 0.f;
}

// ---------------------------- precompute U, V ------------------------------
// U[n] = x[n] @ (W1[0:64] - W1[64:128]) + b1 ;  V[n] = x[n] @ W1[64:128]
#define PNPW 4
#define PWARPS 16
#define PTHREADS 512
#define P_WU  0            // 64*128
#define P_WV  8192         // 64*128
#define P_B1  16384        // 128
#define P_BUF 16512        // 16 warps * 4 nodes * 64
#define P_SMEMF 20608
#define P_SMEMB (P_SMEMF * 4)

__global__ __launch_bounds__(PTHREADS, 1)
void pre_kernel(const float* __restrict__ x, const float* __restrict__ W1,
                const float* __restrict__ b1, int N) {
    extern __shared__ float sm[];
    int tid = threadIdx.x;
    for (int idx = tid; idx < 64 * 128; idx += PTHREADS) {
        float a = W1[idx];
        float b = W1[idx + 64 * 128];
        sm[P_WU + idx] = a - b;
        sm[P_WV + idx] = b;
    }
    for (int t = tid; t < 128; t += PTHREADS) sm[P_B1 + t] = b1[t];
    __syncthreads();

    int warp = tid >> 5, lane = tid & 31;
    float* buf = sm + P_BUF + warp * (PNPW * 64);
    ull hb0 = pk2(sm[P_B1 + lane*4],     sm[P_B1 + lane*4 + 1]);
    ull hb1 = pk2(sm[P_B1 + lane*4 + 2], sm[P_B1 + lane*4 + 3]);
    const float* wup = sm + P_WU + lane * 4;
    const float* wvp = sm + P_WV + lane * 4;

    int ngroups = (N + PNPW - 1) / PNPW;
    int gwarp = blockIdx.x * PWARPS + warp;
    int nwarp = gridDim.x * PWARPS;

    for (int g = gwarp; g < ngroups; g += nwarp) {
        int base = g * PNPW;
        #pragma unroll
        for (int u = 0; u < PNPW; u++) {
            int n = base + u;
            if (lane < 16) {
                const float4* xn = (const float4*)(x + (size_t)(n < N ? n : 0) * 64);
                float4 a = (n < N) ? xn[lane] : make_float4(0.f, 0.f, 0.f, 0.f);
                ((float4*)(buf + u * 64))[lane] = a;
            }
        }
        __syncwarp();

        ull aU0[PNPW], aU1[PNPW], aV0[PNPW], aV1[PNPW];
        #pragma unroll
        for (int u = 0; u < PNPW; u++) { aU0[u] = hb0; aU1[u] = hb1; aV0[u] = 0; aV1[u] = 0; }

        #pragma unroll 2
        for (int k = 0; k < 64; k += 2) {
            float4 uA = *(const float4*)(wup + k * 128);
            float4 uB = *(const float4*)(wup + (k + 1) * 128);
            float4 vA = *(const float4*)(wvp + k * 128);
            float4 vB = *(const float4*)(wvp + (k + 1) * 128);
            ull uA01 = pk2(uA.x, uA.y), uA23 = pk2(uA.z, uA.w);
            ull uB01 = pk2(uB.x, uB.y), uB23 = pk2(uB.z, uB.w);
            ull vA01 = pk2(vA.x, vA.y), vA23 = pk2(vA.z, vA.w);
            ull vB01 = pk2(vB.x, vB.y), vB23 = pk2(vB.z, vB.w);
            #pragma unroll
            for (int u = 0; u < PNPW; u++) {
                float2 xv = *(const float2*)(buf + u * 64 + k);
                ull x0 = pk2(xv.x, xv.x);
                ull x1 = pk2(xv.y, xv.y);
                aU0[u] = ffma2(uA01, x0, aU0[u]);
                aU1[u] = ffma2(uA23, x0, aU1[u]);
                aV0[u] = ffma2(vA01, x0, aV0[u]);
                aV1[u] = ffma2(vA23, x0, aV1[u]);
                aU0[u] = ffma2(uB01, x1, aU0[u]);
                aU1[u] = ffma2(uB23, x1, aU1[u]);
                aV0[u] = ffma2(vB01, x1, aV0[u]);
                aV1[u] = ffma2(vB23, x1, aV1[u]);
            }
        }
        #pragma unroll
        for (int u = 0; u < PNPW; u++) {
            int n = base + u;
            if (n < N) {
                float2 p, q;
                p = upk2(aU0[u]); q = upk2(aU1[u]);
                *(float4*)(g_u + (size_t)n * 128 + lane * 4) = make_float4(p.x, p.y, q.x, q.y);
                p = upk2(aV0[u]); q = upk2(aV1[u]);
                *(float4*)(g_v + (size_t)n * 128 + lane * 4) = make_float4(p.x, p.y, q.x, q.y);
            }
        }
        __syncwarp();
    }
}

// ---------------------------- edge kernel ----------------------------------
#define EPW 8
#define EWARPS 16
#define ETHREADS 512
#define E_WP   0            // 3*128 rel-pos weight rows
#define E_W2   384          // 128*64
#define E_B2   8576         // 64
#define E_BUF  8640         // 16 warps * 8 edges * 128
#define E_IDX  25024        // 16 warps * 8 ints
#define E_SMEMF 25152
#define E_SMEMB (E_SMEMF * 4)

__global__ __launch_bounds__(ETHREADS, 1)
void edge_kernel(const float* __restrict__ pos,
                 const int* __restrict__ idxI, const int* __restrict__ idxJ,
                 const float* __restrict__ W1, const float* __restrict__ W2,
                 const float* __restrict__ b2, int E) {
    extern __shared__ float sm[];
    int tid = threadIdx.x;

    for (int t = tid; t < 384; t += ETHREADS) sm[E_WP + t] = W1[128 * 128 + t];
    {
        float4* d2 = (float4*)(sm + E_W2); const float4* s2 = (const float4*)W2;
        for (int t = tid; t < 2048; t += ETHREADS) d2[t] = s2[t];
        float4* d3 = (float4*)(sm + E_B2); const float4* s3 = (const float4*)b2;
        for (int t = tid; t < 16; t += ETHREADS) d3[t] = s3[t];
    }
    __syncthreads();

    int warp = tid >> 5, lane = tid & 31;
    float* buf = sm + E_BUF + warp * (EPW * 128);
    int* sidx = (int*)(sm + E_IDX) + warp * EPW;

    ull mb = pk2(sm[E_B2 + lane*2], sm[E_B2 + lane*2 + 1]);
    const float* w2p = sm + E_W2 + lane*2;
    float4 wp0 = *(const float4*)(sm + E_WP + 0 * 128 + lane * 4);
    float4 wp1 = *(const float4*)(sm + E_WP + 1 * 128 + lane * 4);
    float4 wp2 = *(const float4*)(sm + E_WP + 2 * 128 + lane * 4);

    int ngroups = (E + EPW - 1) / EPW;
    int gwarp = blockIdx.x * EWARPS + warp;
    int nwarp = gridDim.x * EWARPS;

    for (int g = gwarp; g < ngroups; g += nwarp) {
        int base = g * EPW;

        // ---- batch index loads (all LDGs in flight together) ----
        int ii[EPW], jj[EPW];
        #pragma unroll
        for (int e = 0; e < EPW; e++) {
            int ei = base + e;
            bool ok = ei < E;
            ii[e] = ok ? idxI[ei] : -1;
            jj[e] = ok ? idxJ[ei] : 0;
        }
        if (lane == 0) {
            #pragma unroll
            for (int e = 0; e < EPW; e++) sidx[e] = ii[e];
        }

        // ---- batch U/V/pos gathers, then compute hidden ----
        float4 uu[EPW], vv[EPW];
        float p0v[EPW], p1v[EPW], p2v[EPW];
        #pragma unroll
        for (int e = 0; e < EPW; e++) {
            int i = (ii[e] >= 0) ? ii[e] : 0;
            int j = jj[e];
            uu[e] = *(const float4*)(g_u + (size_t)i * 128 + lane * 4);
            vv[e] = *(const float4*)(g_v + (size_t)j * 128 + lane * 4);
            p0v[e] = pos[(size_t)j*3 + 0] - pos[(size_t)i*3 + 0];
            p1v[e] = pos[(size_t)j*3 + 1] - pos[(size_t)i*3 + 1];
            p2v[e] = pos[(size_t)j*3 + 2] - pos[(size_t)i*3 + 2];
        }
        #pragma unroll
        for (int e = 0; e < EPW; e++) {
            if (ii[e] >= 0) {
                float4 h;
                h.x = uu[e].x + vv[e].x + p0v[e]*wp0.x + p1v[e]*wp1.x + p2v[e]*wp2.x;
                h.y = uu[e].y + vv[e].y + p0v[e]*wp0.y + p1v[e]*wp1.y + p2v[e]*wp2.y;
                h.z = uu[e].z + vv[e].z + p0v[e]*wp0.z + p1v[e]*wp1.z + p2v[e]*wp2.z;
                h.w = uu[e].w + vv[e].w + p0v[e]*wp0.w + p1v[e]*wp1.w + p2v[e]*wp2.w;
                *(float4*)(buf + e*128 + lane*4) =
                    make_float4(fmaxf(h.x,0.f), fmaxf(h.y,0.f), fmaxf(h.z,0.f), fmaxf(h.w,0.f));
            } else {
                *(float4*)(buf + e*128 + lane*4) = make_float4(0.f, 0.f, 0.f, 0.f);
            }
        }
        __syncwarp();

        // ---- msg = hidden @ W2 + b2 ; lane owns cols 2l, 2l+1 ----
        ull m[EPW];
        #pragma unroll
        for (int e = 0; e < EPW; e++) m[e] = mb;
        #pragma unroll 2
        for (int k = 0; k < 128; k += 2) {
            float2 wA = *(const float2*)(w2p + k * 64);
            float2 wB = *(const float2*)(w2p + (k + 1) * 64);
            ull wAp = pk2(wA.x, wA.y);
            ull wBp = pk2(wB.x, wB.y);
            #pragma unroll
            for (int e = 0; e < EPW; e++) {
                float2 h = *(const float2*)(buf + e*128 + k);
                m[e] = ffma2(wAp, pk2(h.x, h.x), m[e]);
                m[e] = ffma2(wBp, pk2(h.y, h.y), m[e]);
            }
        }

        // ---- scatter-add: scalar atomics (R5-proven) ----
        #pragma unroll
        for (int e = 0; e < EPW; e++) {
            int i = sidx[e];
            if (i >= 0) {
                float2 r = upk2(m[e]);
                float* dst = g_aggr + (size_t)i * 64 + lane * 2;
                atomicAdd(dst,     r.x);
                atomicAdd(dst + 1, r.y);
            }
        }
        if (lane < EPW) {
            int i = sidx[lane];
            if (i >= 0) atomicAdd(g_cnt + i, 1.0f);
        }
        __syncwarp();
    }
}

// ---------------------------- node kernel (unchanged, proven) --------------
#define NPW 8
#define NWARPS 16
#define NTHREADS 512
#define N_W3   0
#define N_B3   16384
#define N_W4   16512
#define N_B4   24704
#define N_BUF  24768
#define N_SMEMF 41152
#define N_SMEMB (N_SMEMF * 4)

__global__ __launch_bounds__(NTHREADS, 1)
void node_kernel(const float* __restrict__ x,
                 const float* __restrict__ W3, const float* __restrict__ b3,
                 const float* __restrict__ W4, const float* __restrict__ b4,
                 float* __restrict__ out, int N) {
    extern __shared__ float sm[];
    int tid = threadIdx.x;
    {
        float4* d = (float4*)(sm + N_W3); const float4* s = (const float4*)W3;
        for (int t = tid; t < 4096; t += NTHREADS) d[t] = s[t];
        float4* d1 = (float4*)(sm + N_B3); const float4* s1 = (const float4*)b3;
        for (int t = tid; t < 32; t += NTHREADS) d1[t] = s1[t];
        float4* d2 = (float4*)(sm + N_W4); const float4* s2 = (const float4*)W4;
        for (int t = tid; t < 2048; t += NTHREADS) d2[t] = s2[t];
        float4* d3 = (float4*)(sm + N_B4); const float4* s3 = (const float4*)b4;
        for (int t = tid; t < 16; t += NTHREADS) d3[t] = s3[t];
    }
    __syncthreads();

    int warp = tid >> 5, lane = tid & 31;
    float* buf = sm + N_BUF + warp * (NPW * 128);
    ull hb0 = pk2(sm[N_B3 + lane*4],     sm[N_B3 + lane*4 + 1]);
    ull hb1 = pk2(sm[N_B3 + lane*4 + 2], sm[N_B3 + lane*4 + 3]);
    ull ob  = pk2(sm[N_B4 + lane*2],     sm[N_B4 + lane*2 + 1]);
    const float* w3p = sm + N_W3 + lane*4;
    const float* w4p = sm + N_W4 + lane*2;

    int ngroups = (N + NPW - 1) / NPW;
    int gwarp = blockIdx.x * NWARPS + warp;
    int nwarp = gridDim.x * NWARPS;

    for (int g = gwarp; g < ngroups; g += nwarp) {
        int base = g * NPW;

        #pragma unroll
        for (int u = 0; u < NPW; u++) {
            int n = base + u;
            if (n < N) {
                if (lane < 16) {
                    float inv = 1.0f / fmaxf(g_cnt[n], 1.0f);
                    const float4* xn = (const float4*)(x + (size_t)n * 64);
                    const float4* an = (const float4*)(g_aggr + (size_t)n * 64);
                    float4 a = xn[lane], b = an[lane];
                    float4* pb = (float4*)(buf + u * 128);
                    pb[lane] = a;
                    pb[16 + lane] = make_float4(b.x*inv, b.y*inv, b.z*inv, b.w*inv);
                }
            } else {
                for (int t = lane; t < 128; t += 32) buf[u*128 + t] = 0.f;
            }
        }
        __syncwarp();

        ull a0[NPW], a1[NPW];
        #pragma unroll
        for (int u = 0; u < NPW; u++) { a0[u] = hb0; a1[u] = hb1; }
        #pragma unroll 2
        for (int k = 0; k < 128; k += 2) {
            float4 wA = *(const float4*)(w3p + k * 128);
            float4 wB = *(const float4*)(w3p + (k + 1) * 128);
            ull wA01 = pk2(wA.x, wA.y), wA23 = pk2(wA.z, wA.w);
            ull wB01 = pk2(wB.x, wB.y), wB23 = pk2(wB.z, wB.w);
            #pragma unroll
            for (int u = 0; u < NPW; u++) {
                float2 v = *(const float2*)(buf + u*128 + k);
                ull v0 = pk2(v.x, v.x);
                ull v1 = pk2(v.y, v.y);
                a0[u] = ffma2(wA01, v0, a0[u]);
                a1[u] = ffma2(wA23, v0, a1[u]);
                a0[u] = ffma2(wB01, v1, a0[u]);
                a1[u] = ffma2(wB23, v1, a1[u]);
            }
        }
        __syncwarp();
        #pragma unroll
        for (int u = 0; u < NPW; u++) {
            float2 p = upk2(a0[u]);
            float2 q = upk2(a1[u]);
            *(float4*)(buf + u*128 + lane*4) =
                make_float4(fmaxf(p.x,0.f), fmaxf(p.y,0.f), fmaxf(q.x,0.f), fmaxf(q.y,0.f));
        }
        __syncwarp();

        ull m[NPW];
        #pragma unroll
        for (int u = 0; u < NPW; u++) m[u] = ob;
        #pragma unroll 2
        for (int k = 0; k < 128; k += 2) {
            float2 wA = *(const float2*)(w4p + k * 64);
            float2 wB = *(const float2*)(w4p + (k + 1) * 64);
            ull wAp = pk2(wA.x, wA.y);
            ull wBp = pk2(wB.x, wB.y);
            #pragma unroll
            for (int u = 0; u < NPW; u++) {
                float2 h = *(const float2*)(buf + u*128 + k);
                m[u] = ffma2(wAp, pk2(h.x, h.x), m[u]);
                m[u] = ffma2(wBp, pk2(h.y, h.y), m[u]);
            }
        }
        #pragma unroll
        for (int u = 0; u < NPW; u++) {
            int n = base + u;
            if (n < N) {
                float2 rr = upk2(m[u]);
                *(float2*)(out + (size_t)n * 64 + lane * 2) = rr;
            }
        }
        __syncwarp();
    }
}

// ---------------------------- launch ---------------------------------------
extern "C" void kernel_launch(void* const* d_in, const int* in_sizes, int n_in,
                              void* d_out, int out_size) {
    const float* x   = (const float*)d_in[0];
    const float* pos = (const float*)d_in[1];
    const int*   ei  = (const int*)d_in[2];
    const float* W1  = (const float*)d_in[3];
    const float* b1  = (const float*)d_in[4];
    const float* W2  = (const float*)d_in[5];
    const float* b2  = (const float*)d_in[6];
    const float* W3  = (const float*)d_in[7];
    const float* b3  = (const float*)d_in[8];
    const float* W4  = (const float*)d_in[9];
    const float* b4  = (const float*)d_in[10];
    int N = in_sizes[0] / 64;
    int E = in_sizes[2] / 2;

    cudaFuncSetAttribute(pre_kernel,  cudaFuncAttributeMaxDynamicSharedMemorySize, P_SMEMB);
    cudaFuncSetAttribute(edge_kernel, cudaFuncAttributeMaxDynamicSharedMemorySize, E_SMEMB);
    cudaFuncSetAttribute(node_kernel, cudaFuncAttributeMaxDynamicSharedMemorySize, N_SMEMB);

    zero_kernel<<<512, 256>>>(N * 16, N);
    pre_kernel<<<304, PTHREADS, P_SMEMB>>>(x, W1, b1, N);
    edge_kernel<<<304, ETHREADS, E_SMEMB>>>(pos, ei, ei + E, W1, W2, b2, E);
    node_kernel<<<304, NTHREADS, N_SMEMB>>>(x, W3, b3, W4, b4, (float*)d_out, N);
}